// round 13
// baseline (speedup 1.0000x reference)
#include <cuda_runtime.h>
#include <cstdint>

typedef unsigned long long ull;

#define B_     16
#define D_     4096
#define NKV    8
#define HD     128
#define SEQ    4096
#define KSPLIT 64
#define KSLICE 64
#define ASTG   5
#define GSTG   6
#define GKROW  4
#define GCOLS  512
#define GWARPS 4

// ---------------- scratch ----------------
// GEMM partials ROW-PAIR interleaved: float idx ((ks*8+p)*2N) + col*2 + e, row=2p+e
__device__ float g_q   [B_ * D_];
__device__ float g_kn  [B_ * NKV * HD];
__device__ float g_vn  [B_ * NKV * HD];
__device__ float g_attn[B_ * D_];
__device__ ull   g_xp  [4096 * 8];       // x row-pairs: [k][p] = (x[2p][k], x[2p+1][k])
__device__ float g_Pq  [KSPLIT * B_ * D_];
__device__ float g_Pk  [KSPLIT * B_ * NKV * HD];
__device__ float g_Pv  [KSPLIT * B_ * NKV * HD];
__device__ float g_Po  [KSPLIT * B_ * D_];

// ---------------- packed f32x2 helpers ----------------
__device__ __forceinline__ ull ffma2(ull a, ull b, ull c) {
    ull d; asm("fma.rn.f32x2 %0,%1,%2,%3;" : "=l"(d) : "l"(a), "l"(b), "l"(c)); return d;
}
__device__ __forceinline__ ull fmul2(ull a, ull b) {
    ull d; asm("mul.rn.f32x2 %0,%1,%2;" : "=l"(d) : "l"(a), "l"(b)); return d;
}
__device__ __forceinline__ ull fadd2(ull a, ull b) {
    ull d; asm("add.rn.f32x2 %0,%1,%2;" : "=l"(d) : "l"(a), "l"(b)); return d;
}
__device__ __forceinline__ ull pack2(float x, float y) {
    ull d; asm("mov.b64 %0,{%1,%2};" : "=l"(d) : "f"(x), "f"(y)); return d;
}
__device__ __forceinline__ float2 unpack2(ull a) {
    float2 r; asm("mov.b64 {%0,%1},%2;" : "=f"(r.x), "=f"(r.y) : "l"(a)); return r;
}
__device__ __forceinline__ ull redshfl2(ull v, int m) {
    float2 f = unpack2(v);
    float x = __shfl_xor_sync(0xffffffffu, f.x, m);
    float y = __shfl_xor_sync(0xffffffffu, f.y, m);
    return fadd2(v, pack2(x, y));
}

#define CP16(dst, src) asm volatile("cp.async.cg.shared.global [%0],[%1],16;\n" :: "r"(dst), "l"(src) : "memory")
#define CPCOMMIT()     asm volatile("cp.async.commit_group;\n" ::: "memory")
#define CPWAIT4()      asm volatile("cp.async.wait_group 4;\n" ::: "memory")

// ---------------- x pair-pack: g_xp[k][p] = (src[2p][k], src[2p+1][k]) ----------------
__global__ void __launch_bounds__(256) xpair(const float* __restrict__ src, int use_attn)
{
    const float* s = use_attn ? g_attn : src;
    int e = blockIdx.x * 256 + threadIdx.x;       // 32768
    int k = e >> 3, p = e & 7;
    g_xp[e] = pack2(s[(2 * p) * 4096 + k], s[(2 * p + 1) * 4096 + k]);
}

// ---------------- skinny GEMM: out[16,N] = X[16,4096] @ W[4096,N] ----------------
// 128-thread blocks, 4 warps x 128 cols, cp.async 6-stage warp-private ring.
// Row-pair packed accumulators; x comes from g_xp via UNIFORM global loads
// (L1-resident, 1 line per LDG.128) — zero x traffic on the smem crossbar.
// No __syncthreads anywhere.
__global__ void __launch_bounds__(128, 4) gemm16(const float* __restrict__ W0,
                                                 const float* __restrict__ W1,
                                                 const float* __restrict__ W2,
                                                 int mode)
{
    extern __shared__ char gsm[];
    float* ring = (float*)gsm;                    // [GSTG][4 warps][4k][512B] = 48KB

    int t = blockIdx.x, ks = blockIdx.y;
    const float* W; float* P; int N, ct;
    if (mode == 0) {
        if (t < 8)       { W = W0; P = g_Pq; N = 4096; ct = t; }
        else if (t < 10) { W = W1; P = g_Pk; N = 1024; ct = t - 8; }
        else             { W = W2; P = g_Pv; N = 1024; ct = t - 10; }
    } else {
        W = W0; P = g_Po; N = 4096; ct = t;
    }

    int tid = threadIdx.x, wid = tid >> 5, lane = tid & 31;
    int kbase = ks * KSLICE;
    int colbase = ct * GCOLS + wid * 128;

    const float* Wbase = W + (size_t)kbase * N + colbase + lane * 4;
    uint32_t wbuf0 = (uint32_t)__cvta_generic_to_shared(ring) + wid * 2048 + lane * 16;

    auto cpstage = [&](int s, int slot) {
        const float* srow = Wbase + (size_t)(s * GKROW) * N;
        uint32_t d = wbuf0 + slot * (GWARPS * 2048);
        CP16(d,        srow);
        CP16(d + 512,  srow + N);
        CP16(d + 1024, srow + 2 * (size_t)N);
        CP16(d + 1536, srow + 3 * (size_t)N);
    };

    #pragma unroll
    for (int s = 0; s < GSTG; s++) { cpstage(s, s); CPCOMMIT(); }

    ull acc[8][4] = {};
    const ull* xbase = g_xp + (size_t)kbase * 8;

    #pragma unroll 1
    for (int s = 0; s < KSLICE / GKROW; s++) {       // 16 stages
        CPWAIT4();
        int slot = s % GSTG;
        const float* wsp = ring + (size_t)(slot * GWARPS + wid) * 512 + lane * 4;
        const ull* xsp = xbase + (size_t)s * (GKROW * 8);
        #pragma unroll
        for (int k = 0; k < GKROW; k++) {
            float4 w4 = *(const float4*)(wsp + k * 128);
            ull ws0 = pack2(w4.x, w4.x), ws1 = pack2(w4.y, w4.y);
            ull ws2 = pack2(w4.z, w4.z), ws3 = pack2(w4.w, w4.w);
            const ull* xk = xsp + k * 8;
            ulonglong2 x01 = *(const ulonglong2*)(xk);       // uniform LDG.128
            ulonglong2 x23 = *(const ulonglong2*)(xk + 2);
            ulonglong2 x45 = *(const ulonglong2*)(xk + 4);
            ulonglong2 x67 = *(const ulonglong2*)(xk + 6);
            ull xv[8] = {x01.x, x01.y, x23.x, x23.y, x45.x, x45.y, x67.x, x67.y};
            #pragma unroll
            for (int p = 0; p < 8; p++) {
                acc[p][0] = ffma2(xv[p], ws0, acc[p][0]);
                acc[p][1] = ffma2(xv[p], ws1, acc[p][1]);
                acc[p][2] = ffma2(xv[p], ws2, acc[p][2]);
                acc[p][3] = ffma2(xv[p], ws3, acc[p][3]);
            }
        }
        if (s + GSTG < KSLICE / GKROW) cpstage(s + GSTG, slot);
        CPCOMMIT();
    }

    #pragma unroll
    for (int p = 0; p < 8; p++) {
        float* o = P + ((size_t)ks * 8 + p) * (2 * (size_t)N) + (size_t)(colbase + lane * 4) * 2;
        ulonglong2 s1; s1.x = acc[p][0]; s1.y = acc[p][1];
        ulonglong2 s2; s2.x = acc[p][2]; s2.y = acc[p][3];
        *(ulonglong2*)(o)     = s1;
        *(ulonglong2*)(o + 4) = s2;
    }
}

// ---------------- combine K-split partials + l2norm ----------------
__global__ void __launch_bounds__(128) norm_combine()
{
    __shared__ float red[4];
    int blk = blockIdx.x, d = threadIdx.x;
    float v = 0.f; float* outp; bool donorm;
    if (blk < 512) {
        int b = blk >> 5, h = blk & 31;
        const float* p = g_Pq + (size_t)(b >> 1) * 8192 + (size_t)(h * 128 + d) * 2 + (b & 1);
        #pragma unroll
        for (int ks = 0; ks < KSPLIT; ks++) v += p[(size_t)ks * 8 * 8192];
        outp = g_q + (size_t)b * 4096 + h * 128 + d; donorm = true;
    } else if (blk < 640) {
        int idx = blk - 512; int b = idx >> 3, gg = idx & 7;
        const float* p = g_Pk + (size_t)(b >> 1) * 2048 + (size_t)(gg * 128 + d) * 2 + (b & 1);
        #pragma unroll
        for (int ks = 0; ks < KSPLIT; ks++) v += p[(size_t)ks * 8 * 2048];
        outp = g_kn + (size_t)(b * 8 + gg) * 128 + d; donorm = true;
    } else {
        int idx = blk - 640; int b = idx >> 3, gg = idx & 7;
        const float* p = g_Pv + (size_t)(b >> 1) * 2048 + (size_t)(gg * 128 + d) * 2 + (b & 1);
        #pragma unroll
        for (int ks = 0; ks < KSPLIT; ks++) v += p[(size_t)ks * 8 * 2048];
        outp = g_vn + (size_t)(b * 8 + gg) * 128 + d; donorm = false;
    }
    float s = v * v;
    #pragma unroll
    for (int m = 16; m >= 1; m >>= 1) s += __shfl_xor_sync(0xffffffffu, s, m);
    if ((d & 31) == 0) red[d >> 5] = s;
    __syncthreads();
    if (donorm) {
        float tot = red[0] + red[1] + red[2] + red[3];
        v *= rsqrtf(tot * (1.0f / 128.0f) + 1e-6f);
    }
    *outp = v;
}

// ---------------- attention: cp.async 5-stage warp-private pipeline ----------------
__global__ void __launch_bounds__(512, 1) attention(const float* __restrict__ CK,
                                                    const float* __restrict__ CV)
{
    extern __shared__ float sm[];
    float* ksm  = sm;                        // [ASTG][32][128]
    float* vsm  = sm + ASTG * 32 * 128;      // [ASTG][32][128]
    float* part = vsm + ASTG * 32 * 128;     // [16][512]
    float* psum = part + 16 * 512;           // [16][4]

    int g = blockIdx.x, b = blockIdx.y;
    int tid = threadIdx.x, w = tid >> 5, lid = tid & 31;
    int half = lid >> 4, sub = lid & 15;
    int H = w * 2 + half;

    const float* Kb = CK + (size_t)b * (SEQ * NKV * HD) + g * HD + sub * 8;
    const float* Vb = CV + (size_t)b * (SEQ * NKV * HD) + g * HD + sub * 8;
    const float* knrow = g_kn + (b * NKV + g) * HD + sub * 8;
    const float* vnrow = g_vn + (b * NKV + g) * HD + sub * 8;

    uint32_t kdst0 = (uint32_t)__cvta_generic_to_shared(ksm + (size_t)H * 128 + sub * 8);
    uint32_t vdst0 = (uint32_t)__cvta_generic_to_shared(vsm + (size_t)H * 128 + sub * 8);

    const float sc = 0.08838834764831845f;   // 1/sqrt(128)
    ull q2[4][4];
    #pragma unroll
    for (int r = 0; r < 4; r++) {
        const float* qp = g_q + (size_t)b * 4096 + (g * 4 + r) * 128 + sub * 8;
        float4 a = *(const float4*)qp;
        float4 c = *(const float4*)(qp + 4);
        q2[r][0] = pack2(a.x * sc, a.y * sc);
        q2[r][1] = pack2(a.z * sc, a.w * sc);
        q2[r][2] = pack2(c.x * sc, c.y * sc);
        q2[r][3] = pack2(c.z * sc, c.w * sc);
    }

    auto copy_stage = [&](int st, int step) {
        int k = step * 32 + H;
        const float* kp = (k == SEQ - 1) ? knrow : (Kb + (size_t)k * (NKV * HD));
        const float* vp = (k == SEQ - 1) ? vnrow : (Vb + (size_t)k * (NKV * HD));
        uint32_t kd = kdst0 + st * (32 * 128 * 4);
        uint32_t vd = vdst0 + st * (32 * 128 * 4);
        CP16(kd, kp);       CP16(kd + 16, kp + 4);
        CP16(vd, vp);       CP16(vd + 16, vp + 4);
    };

    #pragma unroll
    for (int s = 0; s < ASTG; s++) { copy_stage(s, s); CPCOMMIT(); }

    ull acc[4][4] = {};
    float ssum[4] = {0.f, 0.f, 0.f, 0.f};

    #pragma unroll 1
    for (int i = 0; i < SEQ / 32; i++) {
        CPWAIT4();
        int st = i % ASTG;
        const float* kr = ksm + (size_t)(st * 32 + H) * 128 + sub * 8;
        const float* vr = vsm + (size_t)(st * 32 + H) * 128 + sub * 8;
        ulonglong2 k0 = *(const ulonglong2*)kr;
        ulonglong2 k1 = *(const ulonglong2*)(kr + 4);
        ulonglong2 v0 = *(const ulonglong2*)vr;
        ulonglong2 v1 = *(const ulonglong2*)(vr + 4);

        if (i + ASTG < SEQ / 32) copy_stage(st, i + ASTG);
        CPCOMMIT();

        float p[4];
        #pragma unroll
        for (int r = 0; r < 4; r++) {
            ull tq = fmul2(q2[r][0], k0.x);
            tq = ffma2(q2[r][1], k0.y, tq);
            tq = ffma2(q2[r][2], k1.x, tq);
            tq = ffma2(q2[r][3], k1.y, tq);
            float2 f = unpack2(tq);
            p[r] = f.x + f.y;
        }
        ull p01 = pack2(p[0], p[1]), p23 = pack2(p[2], p[3]);
        #pragma unroll
        for (int m = 1; m <= 8; m <<= 1) {
            p01 = redshfl2(p01, m);
            p23 = redshfl2(p23, m);
        }
        float2 fa = unpack2(p01), fc = unpack2(p23);
        float w0 = __expf(fa.x - 16.0f);
        float w1 = __expf(fa.y - 16.0f);
        float w2 = __expf(fc.x - 16.0f);
        float w3 = __expf(fc.y - 16.0f);
        ssum[0] += w0; ssum[1] += w1; ssum[2] += w2; ssum[3] += w3;
        ull wd;
        wd = pack2(w0, w0);
        acc[0][0] = ffma2(wd, v0.x, acc[0][0]);
        acc[0][1] = ffma2(wd, v0.y, acc[0][1]);
        acc[0][2] = ffma2(wd, v1.x, acc[0][2]);
        acc[0][3] = ffma2(wd, v1.y, acc[0][3]);
        wd = pack2(w1, w1);
        acc[1][0] = ffma2(wd, v0.x, acc[1][0]);
        acc[1][1] = ffma2(wd, v0.y, acc[1][1]);
        acc[1][2] = ffma2(wd, v1.x, acc[1][2]);
        acc[1][3] = ffma2(wd, v1.y, acc[1][3]);
        wd = pack2(w2, w2);
        acc[2][0] = ffma2(wd, v0.x, acc[2][0]);
        acc[2][1] = ffma2(wd, v0.y, acc[2][1]);
        acc[2][2] = ffma2(wd, v1.x, acc[2][2]);
        acc[2][3] = ffma2(wd, v1.y, acc[2][3]);
        wd = pack2(w3, w3);
        acc[3][0] = ffma2(wd, v0.x, acc[3][0]);
        acc[3][1] = ffma2(wd, v0.y, acc[3][1]);
        acc[3][2] = ffma2(wd, v1.x, acc[3][2]);
        acc[3][3] = ffma2(wd, v1.y, acc[3][3]);
    }

    // combine half-warps (key-halves are additive partials) before smem dump
    #pragma unroll
    for (int r = 0; r < 4; r++) {
        #pragma unroll
        for (int j = 0; j < 4; j++)
            acc[r][j] = redshfl2(acc[r][j], 16);
        ssum[r] += __shfl_xor_sync(0xffffffffu, ssum[r], 16);
    }
    if (half == 0) {
        #pragma unroll
        for (int r = 0; r < 4; r++) {
            #pragma unroll
            for (int j = 0; j < 4; j++)
                *(ull*)&part[(size_t)w * 512 + r * 128 + sub * 8 + j * 2] = acc[r][j];
            if (sub == 0) psum[w * 4 + r] = ssum[r];
        }
    }
    __syncthreads();

    int r = tid >> 7;
    float tot = 0.f, ts = 0.f;
    #pragma unroll
    for (int h2 = 0; h2 < 16; h2++) {
        tot += part[(size_t)h2 * 512 + tid];
        ts  += psum[h2 * 4 + r];
    }
    g_attn[(size_t)b * 4096 + g * 512 + tid] = tot / ts;
}

// ---------------- final combine of wo K-split partials ----------------
__global__ void __launch_bounds__(256) combine_out(float* __restrict__ out)
{
    int e = blockIdx.x * 256 + threadIdx.x;
    int b = e >> 12, col = e & 4095;
    const float* p = g_Po + (size_t)(b >> 1) * 8192 + (size_t)col * 2 + (b & 1);
    float v = 0.f;
    #pragma unroll
    for (int ks = 0; ks < KSPLIT; ks++) v += p[(size_t)ks * 8 * 8192];
    out[e] = v;
}

// ---------------- launch ----------------
extern "C" void kernel_launch(void* const* d_in, const int* in_sizes, int n_in,
                              void* d_out, int out_size)
{
    const float* x  = (const float*)d_in[0];
    const float* wq = (const float*)d_in[1];
    const float* wk = (const float*)d_in[2];
    const float* wv = (const float*)d_in[3];
    const float* wo = (const float*)d_in[4];
    const float* ck = (const float*)d_in[5];
    const float* cv = (const float*)d_in[6];

    const int attn_smem = (ASTG * 32 * 128 * 2 + 16 * 512 + 64) * 4;   // 196864 B
    const int gemm_smem = GSTG * GWARPS * 2048;                        // 48KB
    static int smem_set = 0;
    if (!smem_set) {
        cudaFuncSetAttribute(attention, cudaFuncAttributeMaxDynamicSharedMemorySize, attn_smem);
        cudaFuncSetAttribute(gemm16, cudaFuncAttributeMaxDynamicSharedMemorySize, gemm_smem);
        smem_set = 1;
    }

    xpair<<<128, 256>>>(x, 0);
    gemm16<<<dim3(12, KSPLIT), 128, gemm_smem>>>(wq, wk, wv, 0);
    norm_combine<<<768, 128>>>();
    attention<<<dim3(8, 16), 512, attn_smem>>>(ck, cv);
    xpair<<<128, 256>>>(x, 1);
    gemm16<<<dim3(8, KSPLIT), 128, gemm_smem>>>(wo, wo, wo, 1);
    combine_out<<<256, 256>>>((float*)d_out);
}

// round 14
// speedup vs baseline: 1.1336x; 1.1336x over previous
#include <cuda_runtime.h>
#include <cstdint>

typedef unsigned long long ull;

#define B_     16
#define D_     4096
#define NKV    8
#define HD     128
#define SEQ    4096
#define KSPLIT 64
#define KSLICE 64
#define STAGES 4
#define GSTG   6
#define GKROW  4
#define GCOLS  512
#define GWARPS 4

// ---------------- scratch ----------------
// GEMM partials ROW-PAIR interleaved: float idx ((ks*8+p)*2N) + col*2 + e, row=2p+e
__device__ float g_q   [B_ * D_];
__device__ float g_kn  [B_ * NKV * HD];
__device__ float g_vn  [B_ * NKV * HD];
__device__ float g_attn[B_ * D_];
__device__ float g_Pq  [KSPLIT * B_ * D_];
__device__ float g_Pk  [KSPLIT * B_ * NKV * HD];
__device__ float g_Pv  [KSPLIT * B_ * NKV * HD];
__device__ float g_Po  [KSPLIT * B_ * D_];

// ---------------- packed f32x2 helpers ----------------
__device__ __forceinline__ ull ffma2(ull a, ull b, ull c) {
    ull d; asm("fma.rn.f32x2 %0,%1,%2,%3;" : "=l"(d) : "l"(a), "l"(b), "l"(c)); return d;
}
__device__ __forceinline__ ull fmul2(ull a, ull b) {
    ull d; asm("mul.rn.f32x2 %0,%1,%2;" : "=l"(d) : "l"(a), "l"(b)); return d;
}
__device__ __forceinline__ ull fadd2(ull a, ull b) {
    ull d; asm("add.rn.f32x2 %0,%1,%2;" : "=l"(d) : "l"(a), "l"(b)); return d;
}
__device__ __forceinline__ ull pack2(float x, float y) {
    ull d; asm("mov.b64 %0,{%1,%2};" : "=l"(d) : "f"(x), "f"(y)); return d;
}
__device__ __forceinline__ float2 unpack2(ull a) {
    float2 r; asm("mov.b64 {%0,%1},%2;" : "=f"(r.x), "=f"(r.y) : "l"(a)); return r;
}
__device__ __forceinline__ ull redshfl2(ull v, int m) {
    float2 f = unpack2(v);
    float x = __shfl_xor_sync(0xffffffffu, f.x, m);
    float y = __shfl_xor_sync(0xffffffffu, f.y, m);
    return fadd2(v, pack2(x, y));
}

#define CP16(dst, src) asm volatile("cp.async.cg.shared.global [%0],[%1],16;\n" :: "r"(dst), "l"(src) : "memory")
#define CPCOMMIT()     asm volatile("cp.async.commit_group;\n" ::: "memory")
#define CPWAIT3()      asm volatile("cp.async.wait_group 3;\n" ::: "memory")
#define CPWAIT4()      asm volatile("cp.async.wait_group 4;\n" ::: "memory")

// ---------------- skinny GEMM: out[16,N] = X[16,4096] @ W[4096,N] ----------------
// 128-thread blocks, 4 warps x 128 cols, cp.async 6-stage warp-private ring.
// Tiling p=4 pairs x c=8 cols per lane: lane = (pair-half ph = lane>>4) x
// (col-group cg = lane&15). x broadcasts: 8 LDS.128/stage (was 16).
__global__ void __launch_bounds__(128, 4) gemm16(const float* __restrict__ Xin,
                                                 const float* __restrict__ W0,
                                                 const float* __restrict__ W1,
                                                 const float* __restrict__ W2,
                                                 int mode)
{
    extern __shared__ char gsm[];
    float* ring = (float*)gsm;                                // [GSTG][4 warps][4k][512B] = 48KB
    ull*   xs2  = (ull*)(gsm + GSTG * GWARPS * 2048);         // [KSLICE][8 row-pairs] = 4KB

    int t = blockIdx.x, ks = blockIdx.y;
    const float* X = Xin; const float* W; float* P; int N, ct;
    if (mode == 0) {
        if (t < 8)       { W = W0; P = g_Pq; N = 4096; ct = t; }
        else if (t < 10) { W = W1; P = g_Pk; N = 1024; ct = t - 8; }
        else             { W = W2; P = g_Pv; N = 1024; ct = t - 10; }
    } else {
        W = W0; P = g_Po; N = 4096; ct = t; X = g_attn;
    }

    int tid = threadIdx.x, wid = tid >> 5, lane = tid & 31;
    int ph = lane >> 4;            // pair-half: pairs ph*4 .. ph*4+3
    int cg = lane & 15;            // col-group: cols cg*8 .. cg*8+7
    int kbase = ks * KSLICE;
    int colbase = ct * GCOLS + wid * 128;

    const float* Wbase = W + (size_t)kbase * N + colbase + lane * 4;
    uint32_t wbuf0 = (uint32_t)__cvta_generic_to_shared(ring) + wid * 2048 + lane * 16;

    auto cpstage = [&](int s, int slot) {
        const float* srow = Wbase + (size_t)(s * GKROW) * N;
        uint32_t d = wbuf0 + slot * (GWARPS * 2048);
        CP16(d,        srow);
        CP16(d + 512,  srow + N);
        CP16(d + 1024, srow + 2 * (size_t)N);
        CP16(d + 1536, srow + 3 * (size_t)N);
    };

    #pragma unroll
    for (int s = 0; s < GSTG; s++) { cpstage(s, s); CPCOMMIT(); }

    // x -> row-pair ulls in smem, layout [k][p]: thread t fills k = t>>1, pairs (t&1)*4..+3
    {
        int k = tid >> 1, p4 = (tid & 1) * 4;
        #pragma unroll
        for (int pp = 0; pp < 4; pp++) {
            int p = p4 + pp;
            float e0 = X[(2 * p) * 4096 + kbase + k];
            float e1 = X[(2 * p + 1) * 4096 + kbase + k];
            xs2[(size_t)k * 8 + p] = pack2(e0, e1);
        }
    }
    __syncthreads();

    ull acc[4][8] = {};    // acc[pp][c] = (out[2(ph*4+pp)][col], out[2(ph*4+pp)+1][col])

    #pragma unroll 1
    for (int s = 0; s < KSLICE / GKROW; s++) {       // 16 stages
        CPWAIT4();
        __syncwarp();
        int slot = s % GSTG;
        const float* wsp = ring + (size_t)(slot * GWARPS + wid) * 512 + cg * 8;
        const ull* xsp = xs2 + (size_t)s * (GKROW * 8) + ph * 4;
        #pragma unroll
        for (int k = 0; k < GKROW; k++) {
            float4 wa = *(const float4*)(wsp + k * 128);
            float4 wb = *(const float4*)(wsp + k * 128 + 4);
            ull ws0 = pack2(wa.x, wa.x), ws1 = pack2(wa.y, wa.y);
            ull ws2 = pack2(wa.z, wa.z), ws3 = pack2(wa.w, wa.w);
            ull ws4 = pack2(wb.x, wb.x), ws5 = pack2(wb.y, wb.y);
            ull ws6 = pack2(wb.z, wb.z), ws7 = pack2(wb.w, wb.w);
            ulonglong2 xA = *(const ulonglong2*)(xsp + k * 8);
            ulonglong2 xB = *(const ulonglong2*)(xsp + k * 8 + 2);
            ull xv[4] = {xA.x, xA.y, xB.x, xB.y};
            #pragma unroll
            for (int pp = 0; pp < 4; pp++) {
                acc[pp][0] = ffma2(xv[pp], ws0, acc[pp][0]);
                acc[pp][1] = ffma2(xv[pp], ws1, acc[pp][1]);
                acc[pp][2] = ffma2(xv[pp], ws2, acc[pp][2]);
                acc[pp][3] = ffma2(xv[pp], ws3, acc[pp][3]);
                acc[pp][4] = ffma2(xv[pp], ws4, acc[pp][4]);
                acc[pp][5] = ffma2(xv[pp], ws5, acc[pp][5]);
                acc[pp][6] = ffma2(xv[pp], ws6, acc[pp][6]);
                acc[pp][7] = ffma2(xv[pp], ws7, acc[pp][7]);
            }
        }
        if (s + GSTG < KSLICE / GKROW) cpstage(s + GSTG, slot);
        CPCOMMIT();
    }

    // store row-pair interleaved: float idx = (ks*8+p)*2N + col*2 + e
    #pragma unroll
    for (int pp = 0; pp < 4; pp++) {
        int p = ph * 4 + pp;
        float* o = P + ((size_t)ks * 8 + p) * (2 * (size_t)N) + (size_t)(colbase + cg * 8) * 2;
        #pragma unroll
        for (int j = 0; j < 4; j++) {
            ulonglong2 sv; sv.x = acc[pp][j * 2]; sv.y = acc[pp][j * 2 + 1];
            *(ulonglong2*)(o + j * 4) = sv;
        }
    }
}

// ---------------- combine K-split partials + l2norm ----------------
__global__ void __launch_bounds__(128) norm_combine()
{
    __shared__ float red[4];
    int blk = blockIdx.x, d = threadIdx.x;
    float v = 0.f; float* outp; bool donorm;
    if (blk < 512) {
        int b = blk >> 5, h = blk & 31;
        const float* p = g_Pq + (size_t)(b >> 1) * 8192 + (size_t)(h * 128 + d) * 2 + (b & 1);
        #pragma unroll
        for (int ks = 0; ks < KSPLIT; ks++) v += p[(size_t)ks * 8 * 8192];
        outp = g_q + (size_t)b * 4096 + h * 128 + d; donorm = true;
    } else if (blk < 640) {
        int idx = blk - 512; int b = idx >> 3, gg = idx & 7;
        const float* p = g_Pk + (size_t)(b >> 1) * 2048 + (size_t)(gg * 128 + d) * 2 + (b & 1);
        #pragma unroll
        for (int ks = 0; ks < KSPLIT; ks++) v += p[(size_t)ks * 8 * 2048];
        outp = g_kn + (size_t)(b * 8 + gg) * 128 + d; donorm = true;
    } else {
        int idx = blk - 640; int b = idx >> 3, gg = idx & 7;
        const float* p = g_Pv + (size_t)(b >> 1) * 2048 + (size_t)(gg * 128 + d) * 2 + (b & 1);
        #pragma unroll
        for (int ks = 0; ks < KSPLIT; ks++) v += p[(size_t)ks * 8 * 2048];
        outp = g_vn + (size_t)(b * 8 + gg) * 128 + d; donorm = false;
    }
    float s = v * v;
    #pragma unroll
    for (int m = 16; m >= 1; m >>= 1) s += __shfl_xor_sync(0xffffffffu, s, m);
    if ((d & 31) == 0) red[d >> 5] = s;
    __syncthreads();
    if (donorm) {
        float tot = red[0] + red[1] + red[2] + red[3];
        v *= rsqrtf(tot * (1.0f / 128.0f) + 1e-6f);
    }
    *outp = v;
}

// ---------------- attention: cp.async 4-stage warp-private pipeline ----------------
__global__ void __launch_bounds__(512, 1) attention(const float* __restrict__ CK,
                                                    const float* __restrict__ CV)
{
    extern __shared__ float sm[];
    float* ksm  = sm;                        // [STAGES][32][128]
    float* vsm  = sm + STAGES * 32 * 128;    // [STAGES][32][128]
    float* part = vsm + STAGES * 32 * 128;   // [32][512]
    float* psum = part + 32 * 512;           // [32][4]

    int g = blockIdx.x, b = blockIdx.y;
    int tid = threadIdx.x, w = tid >> 5, lid = tid & 31;
    int half = lid >> 4, sub = lid & 15;
    int H = w * 2 + half;

    const float* Kb = CK + (size_t)b * (SEQ * NKV * HD) + g * HD + sub * 8;
    const float* Vb = CV + (size_t)b * (SEQ * NKV * HD) + g * HD + sub * 8;
    const float* knrow = g_kn + (b * NKV + g) * HD + sub * 8;
    const float* vnrow = g_vn + (b * NKV + g) * HD + sub * 8;

    uint32_t kdst0 = (uint32_t)__cvta_generic_to_shared(ksm + (size_t)H * 128 + sub * 8);
    uint32_t vdst0 = (uint32_t)__cvta_generic_to_shared(vsm + (size_t)H * 128 + sub * 8);

    const float sc = 0.08838834764831845f;   // 1/sqrt(128)
    ull q2[4][4];
    #pragma unroll
    for (int r = 0; r < 4; r++) {
        const float* qp = g_q + (size_t)b * 4096 + (g * 4 + r) * 128 + sub * 8;
        float4 a = *(const float4*)qp;
        float4 c = *(const float4*)(qp + 4);
        q2[r][0] = pack2(a.x * sc, a.y * sc);
        q2[r][1] = pack2(a.z * sc, a.w * sc);
        q2[r][2] = pack2(c.x * sc, c.y * sc);
        q2[r][3] = pack2(c.z * sc, c.w * sc);
    }

    auto copy_stage = [&](int st, int step) {
        int k = step * 32 + H;
        const float* kp = (k == SEQ - 1) ? knrow : (Kb + (size_t)k * (NKV * HD));
        const float* vp = (k == SEQ - 1) ? vnrow : (Vb + (size_t)k * (NKV * HD));
        uint32_t kd = kdst0 + st * (32 * 128 * 4);
        uint32_t vd = vdst0 + st * (32 * 128 * 4);
        CP16(kd, kp);       CP16(kd + 16, kp + 4);
        CP16(vd, vp);       CP16(vd + 16, vp + 4);
    };

    #pragma unroll
    for (int s = 0; s < STAGES; s++) { copy_stage(s, s); CPCOMMIT(); }

    ull acc[4][4] = {};
    float ssum[4] = {0.f, 0.f, 0.f, 0.f};

    #pragma unroll 1
    for (int i = 0; i < SEQ / 32; i++) {
        CPWAIT3();
        int st = i & (STAGES - 1);
        const float* kr = ksm + (size_t)(st * 32 + H) * 128 + sub * 8;
        const float* vr = vsm + (size_t)(st * 32 + H) * 128 + sub * 8;
        ulonglong2 k0 = *(const ulonglong2*)kr;
        ulonglong2 k1 = *(const ulonglong2*)(kr + 4);
        ulonglong2 v0 = *(const ulonglong2*)vr;
        ulonglong2 v1 = *(const ulonglong2*)(vr + 4);

        if (i + STAGES < SEQ / 32) copy_stage(st, i + STAGES);
        CPCOMMIT();

        float p[4];
        #pragma unroll
        for (int r = 0; r < 4; r++) {
            ull tq = fmul2(q2[r][0], k0.x);
            tq = ffma2(q2[r][1], k0.y, tq);
            tq = ffma2(q2[r][2], k1.x, tq);
            tq = ffma2(q2[r][3], k1.y, tq);
            float2 f = unpack2(tq);
            p[r] = f.x + f.y;
        }
        ull p01 = pack2(p[0], p[1]), p23 = pack2(p[2], p[3]);
        #pragma unroll
        for (int m = 1; m <= 8; m <<= 1) {
            p01 = redshfl2(p01, m);
            p23 = redshfl2(p23, m);
        }
        float2 fa = unpack2(p01), fc = unpack2(p23);
        float w0 = __expf(fa.x - 16.0f);
        float w1 = __expf(fa.y - 16.0f);
        float w2 = __expf(fc.x - 16.0f);
        float w3 = __expf(fc.y - 16.0f);
        ssum[0] += w0; ssum[1] += w1; ssum[2] += w2; ssum[3] += w3;
        ull wd;
        wd = pack2(w0, w0);
        acc[0][0] = ffma2(wd, v0.x, acc[0][0]);
        acc[0][1] = ffma2(wd, v0.y, acc[0][1]);
        acc[0][2] = ffma2(wd, v1.x, acc[0][2]);
        acc[0][3] = ffma2(wd, v1.y, acc[0][3]);
        wd = pack2(w1, w1);
        acc[1][0] = ffma2(wd, v0.x, acc[1][0]);
        acc[1][1] = ffma2(wd, v0.y, acc[1][1]);
        acc[1][2] = ffma2(wd, v1.x, acc[1][2]);
        acc[1][3] = ffma2(wd, v1.y, acc[1][3]);
        wd = pack2(w2, w2);
        acc[2][0] = ffma2(wd, v0.x, acc[2][0]);
        acc[2][1] = ffma2(wd, v0.y, acc[2][1]);
        acc[2][2] = ffma2(wd, v1.x, acc[2][2]);
        acc[2][3] = ffma2(wd, v1.y, acc[2][3]);
        wd = pack2(w3, w3);
        acc[3][0] = ffma2(wd, v0.x, acc[3][0]);
        acc[3][1] = ffma2(wd, v0.y, acc[3][1]);
        acc[3][2] = ffma2(wd, v1.x, acc[3][2]);
        acc[3][3] = ffma2(wd, v1.y, acc[3][3]);
    }

    #pragma unroll
    for (int r = 0; r < 4; r++) {
        #pragma unroll
        for (int j = 0; j < 4; j++)
            *(ull*)&part[(size_t)H * 512 + r * 128 + sub * 8 + j * 2] = acc[r][j];
        if (sub == 0) psum[H * 4 + r] = ssum[r];
    }
    __syncthreads();

    int r = tid >> 7;
    float tot = 0.f, ts = 0.f;
    #pragma unroll
    for (int h2 = 0; h2 < 32; h2++) {
        tot += part[(size_t)h2 * 512 + tid];
        ts  += psum[h2 * 4 + r];
    }
    g_attn[(size_t)b * 4096 + g * 512 + tid] = tot / ts;
}

// ---------------- final combine of wo K-split partials ----------------
__global__ void __launch_bounds__(256) combine_out(float* __restrict__ out)
{
    int e = blockIdx.x * 256 + threadIdx.x;
    int b = e >> 12, col = e & 4095;
    const float* p = g_Po + (size_t)(b >> 1) * 8192 + (size_t)col * 2 + (b & 1);
    float v = 0.f;
    #pragma unroll
    for (int ks = 0; ks < KSPLIT; ks++) v += p[(size_t)ks * 8 * 8192];
    out[e] = v;
}

// ---------------- launch ----------------
extern "C" void kernel_launch(void* const* d_in, const int* in_sizes, int n_in,
                              void* d_out, int out_size)
{
    const float* x  = (const float*)d_in[0];
    const float* wq = (const float*)d_in[1];
    const float* wk = (const float*)d_in[2];
    const float* wv = (const float*)d_in[3];
    const float* wo = (const float*)d_in[4];
    const float* ck = (const float*)d_in[5];
    const float* cv = (const float*)d_in[6];

    const int attn_smem = (STAGES * 32 * 128 * 2 + 32 * 512 + 128) * 4;   // 197120 B
    const int gemm_smem = GSTG * GWARPS * 2048 + KSLICE * 8 * 8;          // 48KB + 4KB
    static int smem_set = 0;
    if (!smem_set) {
        cudaFuncSetAttribute(attention, cudaFuncAttributeMaxDynamicSharedMemorySize, attn_smem);
        cudaFuncSetAttribute(gemm16, cudaFuncAttributeMaxDynamicSharedMemorySize, gemm_smem);
        smem_set = 1;
    }

    gemm16<<<dim3(12, KSPLIT), 128, gemm_smem>>>(x, wq, wk, wv, 0);
    norm_combine<<<768, 128>>>();
    attention<<<dim3(8, 16), 512, attn_smem>>>(ck, cv);
    gemm16<<<dim3(8, KSPLIT), 128, gemm_smem>>>(x, wo, wo, wo, 1);
    combine_out<<<256, 256>>>((float*)d_out);
}

// round 15
// speedup vs baseline: 1.1499x; 1.0145x over previous
#include <cuda_runtime.h>
#include <cstdint>

typedef unsigned long long ull;

#define B_     16
#define D_     4096
#define NKV    8
#define HD     128
#define SEQ    4096
#define KSPLIT 16
#define KSLICE 256
#define STAGES 4
#define GSTG   6
#define GKROW  4
#define GCOLS  512
#define GWARPS 4

// ---------------- scratch ----------------
// GEMM partials ROW-PAIR interleaved: float idx ((ks*8+p)*2N) + col*2 + e, row=2p+e
__device__ float g_q   [B_ * D_];
__device__ float g_kn  [B_ * NKV * HD];
__device__ float g_vn  [B_ * NKV * HD];
__device__ float g_attn[B_ * D_];
__device__ float g_Pq  [KSPLIT * B_ * D_];
__device__ float g_Pk  [KSPLIT * B_ * NKV * HD];
__device__ float g_Pv  [KSPLIT * B_ * NKV * HD];
__device__ float g_Po  [KSPLIT * B_ * D_];

// ---------------- packed f32x2 helpers ----------------
__device__ __forceinline__ ull ffma2(ull a, ull b, ull c) {
    ull d; asm("fma.rn.f32x2 %0,%1,%2,%3;" : "=l"(d) : "l"(a), "l"(b), "l"(c)); return d;
}
__device__ __forceinline__ ull fmul2(ull a, ull b) {
    ull d; asm("mul.rn.f32x2 %0,%1,%2;" : "=l"(d) : "l"(a), "l"(b)); return d;
}
__device__ __forceinline__ ull fadd2(ull a, ull b) {
    ull d; asm("add.rn.f32x2 %0,%1,%2;" : "=l"(d) : "l"(a), "l"(b)); return d;
}
__device__ __forceinline__ ull pack2(float x, float y) {
    ull d; asm("mov.b64 %0,{%1,%2};" : "=l"(d) : "f"(x), "f"(y)); return d;
}
__device__ __forceinline__ float2 unpack2(ull a) {
    float2 r; asm("mov.b64 {%0,%1},%2;" : "=f"(r.x), "=f"(r.y) : "l"(a)); return r;
}
__device__ __forceinline__ ull redshfl2(ull v, int m) {
    float2 f = unpack2(v);
    float x = __shfl_xor_sync(0xffffffffu, f.x, m);
    float y = __shfl_xor_sync(0xffffffffu, f.y, m);
    return fadd2(v, pack2(x, y));
}

#define CP16(dst, src) asm volatile("cp.async.cg.shared.global [%0],[%1],16;\n" :: "r"(dst), "l"(src) : "memory")
#define CPCOMMIT()     asm volatile("cp.async.commit_group;\n" ::: "memory")
#define CPWAIT3()      asm volatile("cp.async.wait_group 3;\n" ::: "memory")
#define CPWAIT4()      asm volatile("cp.async.wait_group 4;\n" ::: "memory")

// ---------------- skinny GEMM: out[16,N] = X[16,4096] @ W[4096,N] ----------------
// 128-thread blocks, 4 warps x 128 cols, cp.async 6-stage warp-private ring.
// Tiling p=4 pairs x c=8 cols per lane (lane = pair-half ph x col-group cg).
// KSPLIT=16 (KSLICE=256) to cut partial-scratch traffic 4x.
__global__ void __launch_bounds__(128, 3) gemm16(const float* __restrict__ Xin,
                                                 const float* __restrict__ W0,
                                                 const float* __restrict__ W1,
                                                 const float* __restrict__ W2,
                                                 int mode)
{
    extern __shared__ char gsm[];
    float* ring = (float*)gsm;                                // [GSTG][4 warps][4k][512B] = 48KB
    ull*   xs2  = (ull*)(gsm + GSTG * GWARPS * 2048);         // [KSLICE][8 row-pairs] = 16KB

    int t = blockIdx.x, ks = blockIdx.y;
    const float* X = Xin; const float* W; float* P; int N, ct;
    if (mode == 0) {
        if (t < 8)       { W = W0; P = g_Pq; N = 4096; ct = t; }
        else if (t < 10) { W = W1; P = g_Pk; N = 1024; ct = t - 8; }
        else             { W = W2; P = g_Pv; N = 1024; ct = t - 10; }
    } else {
        W = W0; P = g_Po; N = 4096; ct = t; X = g_attn;
    }

    int tid = threadIdx.x, wid = tid >> 5, lane = tid & 31;
    int ph = lane >> 4;            // pair-half: pairs ph*4 .. ph*4+3
    int cg = lane & 15;            // col-group: cols cg*8 .. cg*8+7
    int kbase = ks * KSLICE;
    int colbase = ct * GCOLS + wid * 128;

    const float* Wbase = W + (size_t)kbase * N + colbase + lane * 4;
    uint32_t wbuf0 = (uint32_t)__cvta_generic_to_shared(ring) + wid * 2048 + lane * 16;

    auto cpstage = [&](int s, int slot) {
        const float* srow = Wbase + (size_t)(s * GKROW) * N;
        uint32_t d = wbuf0 + slot * (GWARPS * 2048);
        CP16(d,        srow);
        CP16(d + 512,  srow + N);
        CP16(d + 1024, srow + 2 * (size_t)N);
        CP16(d + 1536, srow + 3 * (size_t)N);
    };

    #pragma unroll
    for (int s = 0; s < GSTG; s++) { cpstage(s, s); CPCOMMIT(); }

    // x -> row-pair ulls in smem, layout [k][p]: thread t fills k = 2t, 2t+1, all 8 pairs
    #pragma unroll
    for (int kk = 0; kk < 2; kk++) {
        int k = tid * 2 + kk;
        #pragma unroll
        for (int p = 0; p < 8; p++) {
            float e0 = X[(2 * p) * 4096 + kbase + k];
            float e1 = X[(2 * p + 1) * 4096 + kbase + k];
            xs2[(size_t)k * 8 + p] = pack2(e0, e1);
        }
    }
    __syncthreads();

    ull acc[4][8] = {};    // acc[pp][c] = (out[2(ph*4+pp)][col], out[2(ph*4+pp)+1][col])

    #pragma unroll 1
    for (int s = 0; s < KSLICE / GKROW; s++) {       // 64 stages
        CPWAIT4();
        __syncwarp();
        int slot = s % GSTG;
        const float* wsp = ring + (size_t)(slot * GWARPS + wid) * 512 + cg * 8;
        const ull* xsp = xs2 + (size_t)s * (GKROW * 8) + ph * 4;
        #pragma unroll
        for (int k = 0; k < GKROW; k++) {
            float4 wa = *(const float4*)(wsp + k * 128);
            float4 wb = *(const float4*)(wsp + k * 128 + 4);
            ull ws0 = pack2(wa.x, wa.x), ws1 = pack2(wa.y, wa.y);
            ull ws2 = pack2(wa.z, wa.z), ws3 = pack2(wa.w, wa.w);
            ull ws4 = pack2(wb.x, wb.x), ws5 = pack2(wb.y, wb.y);
            ull ws6 = pack2(wb.z, wb.z), ws7 = pack2(wb.w, wb.w);
            ulonglong2 xA = *(const ulonglong2*)(xsp + k * 8);
            ulonglong2 xB = *(const ulonglong2*)(xsp + k * 8 + 2);
            ull xv[4] = {xA.x, xA.y, xB.x, xB.y};
            #pragma unroll
            for (int pp = 0; pp < 4; pp++) {
                acc[pp][0] = ffma2(xv[pp], ws0, acc[pp][0]);
                acc[pp][1] = ffma2(xv[pp], ws1, acc[pp][1]);
                acc[pp][2] = ffma2(xv[pp], ws2, acc[pp][2]);
                acc[pp][3] = ffma2(xv[pp], ws3, acc[pp][3]);
                acc[pp][4] = ffma2(xv[pp], ws4, acc[pp][4]);
                acc[pp][5] = ffma2(xv[pp], ws5, acc[pp][5]);
                acc[pp][6] = ffma2(xv[pp], ws6, acc[pp][6]);
                acc[pp][7] = ffma2(xv[pp], ws7, acc[pp][7]);
            }
        }
        if (s + GSTG < KSLICE / GKROW) cpstage(s + GSTG, slot);
        CPCOMMIT();
    }

    // store row-pair interleaved: float idx = (ks*8+p)*2N + col*2 + e
    #pragma unroll
    for (int pp = 0; pp < 4; pp++) {
        int p = ph * 4 + pp;
        float* o = P + ((size_t)ks * 8 + p) * (2 * (size_t)N) + (size_t)(colbase + cg * 8) * 2;
        #pragma unroll
        for (int j = 0; j < 4; j++) {
            ulonglong2 sv; sv.x = acc[pp][j * 2]; sv.y = acc[pp][j * 2 + 1];
            *(ulonglong2*)(o + j * 4) = sv;
        }
    }
}

// ---------------- combine K-split partials + l2norm ----------------
__global__ void __launch_bounds__(128) norm_combine()
{
    __shared__ float red[4];
    int blk = blockIdx.x, d = threadIdx.x;
    float v = 0.f; float* outp; bool donorm;
    if (blk < 512) {
        int b = blk >> 5, h = blk & 31;
        const float* p = g_Pq + (size_t)(b >> 1) * 8192 + (size_t)(h * 128 + d) * 2 + (b & 1);
        #pragma unroll
        for (int ks = 0; ks < KSPLIT; ks++) v += p[(size_t)ks * 8 * 8192];
        outp = g_q + (size_t)b * 4096 + h * 128 + d; donorm = true;
    } else if (blk < 640) {
        int idx = blk - 512; int b = idx >> 3, gg = idx & 7;
        const float* p = g_Pk + (size_t)(b >> 1) * 2048 + (size_t)(gg * 128 + d) * 2 + (b & 1);
        #pragma unroll
        for (int ks = 0; ks < KSPLIT; ks++) v += p[(size_t)ks * 8 * 2048];
        outp = g_kn + (size_t)(b * 8 + gg) * 128 + d; donorm = true;
    } else {
        int idx = blk - 640; int b = idx >> 3, gg = idx & 7;
        const float* p = g_Pv + (size_t)(b >> 1) * 2048 + (size_t)(gg * 128 + d) * 2 + (b & 1);
        #pragma unroll
        for (int ks = 0; ks < KSPLIT; ks++) v += p[(size_t)ks * 8 * 2048];
        outp = g_vn + (size_t)(b * 8 + gg) * 128 + d; donorm = false;
    }
    float s = v * v;
    #pragma unroll
    for (int m = 16; m >= 1; m >>= 1) s += __shfl_xor_sync(0xffffffffu, s, m);
    if ((d & 31) == 0) red[d >> 5] = s;
    __syncthreads();
    if (donorm) {
        float tot = red[0] + red[1] + red[2] + red[3];
        v *= rsqrtf(tot * (1.0f / 128.0f) + 1e-6f);
    }
    *outp = v;
}

// ---------------- attention: cp.async 4-stage warp-private pipeline ----------------
__global__ void __launch_bounds__(512, 1) attention(const float* __restrict__ CK,
                                                    const float* __restrict__ CV)
{
    extern __shared__ float sm[];
    float* ksm  = sm;                        // [STAGES][32][128]
    float* vsm  = sm + STAGES * 32 * 128;    // [STAGES][32][128]
    float* part = vsm + STAGES * 32 * 128;   // [32][512]
    float* psum = part + 32 * 512;           // [32][4]

    int g = blockIdx.x, b = blockIdx.y;
    int tid = threadIdx.x, w = tid >> 5, lid = tid & 31;
    int half = lid >> 4, sub = lid & 15;
    int H = w * 2 + half;

    const float* Kb = CK + (size_t)b * (SEQ * NKV * HD) + g * HD + sub * 8;
    const float* Vb = CV + (size_t)b * (SEQ * NKV * HD) + g * HD + sub * 8;
    const float* knrow = g_kn + (b * NKV + g) * HD + sub * 8;
    const float* vnrow = g_vn + (b * NKV + g) * HD + sub * 8;

    uint32_t kdst0 = (uint32_t)__cvta_generic_to_shared(ksm + (size_t)H * 128 + sub * 8);
    uint32_t vdst0 = (uint32_t)__cvta_generic_to_shared(vsm + (size_t)H * 128 + sub * 8);

    const float sc = 0.08838834764831845f;   // 1/sqrt(128)
    ull q2[4][4];
    #pragma unroll
    for (int r = 0; r < 4; r++) {
        const float* qp = g_q + (size_t)b * 4096 + (g * 4 + r) * 128 + sub * 8;
        float4 a = *(const float4*)qp;
        float4 c = *(const float4*)(qp + 4);
        q2[r][0] = pack2(a.x * sc, a.y * sc);
        q2[r][1] = pack2(a.z * sc, a.w * sc);
        q2[r][2] = pack2(c.x * sc, c.y * sc);
        q2[r][3] = pack2(c.z * sc, c.w * sc);
    }

    auto copy_stage = [&](int st, int step) {
        int k = step * 32 + H;
        const float* kp = (k == SEQ - 1) ? knrow : (Kb + (size_t)k * (NKV * HD));
        const float* vp = (k == SEQ - 1) ? vnrow : (Vb + (size_t)k * (NKV * HD));
        uint32_t kd = kdst0 + st * (32 * 128 * 4);
        uint32_t vd = vdst0 + st * (32 * 128 * 4);
        CP16(kd, kp);       CP16(kd + 16, kp + 4);
        CP16(vd, vp);       CP16(vd + 16, vp + 4);
    };

    #pragma unroll
    for (int s = 0; s < STAGES; s++) { copy_stage(s, s); CPCOMMIT(); }

    ull acc[4][4] = {};
    float ssum[4] = {0.f, 0.f, 0.f, 0.f};

    #pragma unroll 1
    for (int i = 0; i < SEQ / 32; i++) {
        CPWAIT3();
        int st = i & (STAGES - 1);
        const float* kr = ksm + (size_t)(st * 32 + H) * 128 + sub * 8;
        const float* vr = vsm + (size_t)(st * 32 + H) * 128 + sub * 8;
        ulonglong2 k0 = *(const ulonglong2*)kr;
        ulonglong2 k1 = *(const ulonglong2*)(kr + 4);
        ulonglong2 v0 = *(const ulonglong2*)vr;
        ulonglong2 v1 = *(const ulonglong2*)(vr + 4);

        if (i + STAGES < SEQ / 32) copy_stage(st, i + STAGES);
        CPCOMMIT();

        float p[4];
        #pragma unroll
        for (int r = 0; r < 4; r++) {
            ull tq = fmul2(q2[r][0], k0.x);
            tq = ffma2(q2[r][1], k0.y, tq);
            tq = ffma2(q2[r][2], k1.x, tq);
            tq = ffma2(q2[r][3], k1.y, tq);
            float2 f = unpack2(tq);
            p[r] = f.x + f.y;
        }
        ull p01 = pack2(p[0], p[1]), p23 = pack2(p[2], p[3]);
        #pragma unroll
        for (int m = 1; m <= 8; m <<= 1) {
            p01 = redshfl2(p01, m);
            p23 = redshfl2(p23, m);
        }
        float2 fa = unpack2(p01), fc = unpack2(p23);
        float w0 = __expf(fa.x - 16.0f);
        float w1 = __expf(fa.y - 16.0f);
        float w2 = __expf(fc.x - 16.0f);
        float w3 = __expf(fc.y - 16.0f);
        ssum[0] += w0; ssum[1] += w1; ssum[2] += w2; ssum[3] += w3;
        ull wd;
        wd = pack2(w0, w0);
        acc[0][0] = ffma2(wd, v0.x, acc[0][0]);
        acc[0][1] = ffma2(wd, v0.y, acc[0][1]);
        acc[0][2] = ffma2(wd, v1.x, acc[0][2]);
        acc[0][3] = ffma2(wd, v1.y, acc[0][3]);
        wd = pack2(w1, w1);
        acc[1][0] = ffma2(wd, v0.x, acc[1][0]);
        acc[1][1] = ffma2(wd, v0.y, acc[1][1]);
        acc[1][2] = ffma2(wd, v1.x, acc[1][2]);
        acc[1][3] = ffma2(wd, v1.y, acc[1][3]);
        wd = pack2(w2, w2);
        acc[2][0] = ffma2(wd, v0.x, acc[2][0]);
        acc[2][1] = ffma2(wd, v0.y, acc[2][1]);
        acc[2][2] = ffma2(wd, v1.x, acc[2][2]);
        acc[2][3] = ffma2(wd, v1.y, acc[2][3]);
        wd = pack2(w3, w3);
        acc[3][0] = ffma2(wd, v0.x, acc[3][0]);
        acc[3][1] = ffma2(wd, v0.y, acc[3][1]);
        acc[3][2] = ffma2(wd, v1.x, acc[3][2]);
        acc[3][3] = ffma2(wd, v1.y, acc[3][3]);
    }

    #pragma unroll
    for (int r = 0; r < 4; r++) {
        #pragma unroll
        for (int j = 0; j < 4; j++)
            *(ull*)&part[(size_t)H * 512 + r * 128 + sub * 8 + j * 2] = acc[r][j];
        if (sub == 0) psum[H * 4 + r] = ssum[r];
    }
    __syncthreads();

    int r = tid >> 7;
    float tot = 0.f, ts = 0.f;
    #pragma unroll
    for (int h2 = 0; h2 < 32; h2++) {
        tot += part[(size_t)h2 * 512 + tid];
        ts  += psum[h2 * 4 + r];
    }
    g_attn[(size_t)b * 4096 + g * 512 + tid] = tot / ts;
}

// ---------------- final combine of wo K-split partials ----------------
__global__ void __launch_bounds__(256) combine_out(float* __restrict__ out)
{
    int e = blockIdx.x * 256 + threadIdx.x;
    int b = e >> 12, col = e & 4095;
    const float* p = g_Po + (size_t)(b >> 1) * 8192 + (size_t)col * 2 + (b & 1);
    float v = 0.f;
    #pragma unroll
    for (int ks = 0; ks < KSPLIT; ks++) v += p[(size_t)ks * 8 * 8192];
    out[e] = v;
}

// ---------------- launch ----------------
extern "C" void kernel_launch(void* const* d_in, const int* in_sizes, int n_in,
                              void* d_out, int out_size)
{
    const float* x  = (const float*)d_in[0];
    const float* wq = (const float*)d_in[1];
    const float* wk = (const float*)d_in[2];
    const float* wv = (const float*)d_in[3];
    const float* wo = (const float*)d_in[4];
    const float* ck = (const float*)d_in[5];
    const float* cv = (const float*)d_in[6];

    const int attn_smem = (STAGES * 32 * 128 * 2 + 32 * 512 + 128) * 4;   // 197120 B
    const int gemm_smem = GSTG * GWARPS * 2048 + KSLICE * 8 * 8;          // 48KB + 16KB
    static int smem_set = 0;
    if (!smem_set) {
        cudaFuncSetAttribute(attention, cudaFuncAttributeMaxDynamicSharedMemorySize, attn_smem);
        cudaFuncSetAttribute(gemm16, cudaFuncAttributeMaxDynamicSharedMemorySize, gemm_smem);
        smem_set = 1;
    }

    gemm16<<<dim3(12, KSPLIT), 128, gemm_smem>>>(x, wq, wk, wv, 0);
    norm_combine<<<768, 128>>>();
    attention<<<dim3(8, 16), 512, attn_smem>>>(ck, cv);
    gemm16<<<dim3(8, KSPLIT), 128, gemm_smem>>>(x, wo, wo, wo, 1);
    combine_out<<<256, 256>>>((float*)d_out);
}